// round 1
// baseline (speedup 1.0000x reference)
#include <cuda_runtime.h>
#include <cstdint>

// Problem constants (QuantizedLinear_67903432949777)
#define K_DIM 4096
#define N_DIM 4096
#define M_DIM 8192            // BATCH * SEQ = 4 * 2048
#define GROUPS 32             // K / 128
#define PACKED_PER_ROW 2048   // K / 2

// 64 MB scratch for dequantized weights, [N][K] row-major fp32.
// __device__ global array (no runtime allocation — harness rules).
__device__ float g_W[(size_t)N_DIM * K_DIM];

// ---------------------------------------------------------------------------
// Kernel 1: dequantize packed int4 -> fp32
// weight_packed: int32 [N, K/2], each element holds ONE byte:
//   low nibble  -> k = 2j   (value - 8)
//   high nibble -> k = 2j+1 (value - 8)
// scale per (row, k/128) group; both nibbles of one packed elem share a group.
// ---------------------------------------------------------------------------
__global__ void dequant_kernel(const int* __restrict__ wp,
                               const float* __restrict__ scales) {
    int idx = blockIdx.x * blockDim.x + threadIdx.x;
    if (idx >= N_DIM * PACKED_PER_ROW) return;
    int o = idx >> 11;        // / 2048
    int j = idx & 2047;
    int p = wp[idx];
    float s = scales[o * GROUPS + (j >> 6)];   // group = (2j)/128 = j/64
    float lo = (float)((p & 15) - 8) * s;
    float hi = (float)(((p >> 4) & 15) - 8) * s;
    // g_W[o*K + 2j] = lo ; g_W[o*K + 2j + 1] = hi  -> one float2 store
    reinterpret_cast<float2*>(g_W)[idx] = make_float2(lo, hi);
}

// ---------------------------------------------------------------------------
// Kernel 2: fp32 SGEMM  out[m][o] = sum_k X[m][k] * W[o][k] + bias[o]
// Block tile 128x128, BK=16, 256 threads, 8x8 per-thread microtile.
// ---------------------------------------------------------------------------
#define BM 128
#define BN 128
#define BK 16

__global__ __launch_bounds__(256, 2)
void sgemm_kernel(const float* __restrict__ X,
                  const float* __restrict__ bias,
                  float* __restrict__ out) {
    __shared__ float Xs[BK][BM + 4];
    __shared__ float Ws[BK][BN + 4];

    const int tid = threadIdx.x;
    const int bm = blockIdx.y * BM;
    const int bn = blockIdx.x * BN;

    const int tm0 = (tid >> 4) * 8;   // 0..120
    const int tn0 = (tid & 15) * 8;   // 0..120

    float acc[8][8];
    #pragma unroll
    for (int i = 0; i < 8; i++)
        #pragma unroll
        for (int j = 0; j < 8; j++)
            acc[i][j] = 0.0f;

    for (int k0 = 0; k0 < K_DIM; k0 += BK) {
        // Load tiles: 128 rows x 16 cols = 512 float4 per matrix, 2 per thread.
        #pragma unroll
        for (int t = 0; t < 2; t++) {
            int lidx = tid + t * 256;      // 0..511
            int row  = lidx >> 2;          // 0..127
            int kq   = (lidx & 3) * 4;     // 0,4,8,12

            float4 vx = *reinterpret_cast<const float4*>(
                &X[(size_t)(bm + row) * K_DIM + k0 + kq]);
            Xs[kq + 0][row] = vx.x;
            Xs[kq + 1][row] = vx.y;
            Xs[kq + 2][row] = vx.z;
            Xs[kq + 3][row] = vx.w;

            float4 vw = *reinterpret_cast<const float4*>(
                &g_W[(size_t)(bn + row) * K_DIM + k0 + kq]);
            Ws[kq + 0][row] = vw.x;
            Ws[kq + 1][row] = vw.y;
            Ws[kq + 2][row] = vw.z;
            Ws[kq + 3][row] = vw.w;
        }
        __syncthreads();

        #pragma unroll
        for (int k = 0; k < BK; k++) {
            float a[8], b[8];
            #pragma unroll
            for (int i = 0; i < 8; i++) a[i] = Xs[k][tm0 + i];
            #pragma unroll
            for (int j = 0; j < 8; j++) b[j] = Ws[k][tn0 + j];
            #pragma unroll
            for (int i = 0; i < 8; i++)
                #pragma unroll
                for (int j = 0; j < 8; j++)
                    acc[i][j] += a[i] * b[j];
        }
        __syncthreads();
    }

    // Epilogue: add bias, vectorized fp32 stores.
    float bv[8];
    #pragma unroll
    for (int j = 0; j < 8; j++) bv[j] = bias[bn + tn0 + j];

    #pragma unroll
    for (int i = 0; i < 8; i++) {
        size_t base = (size_t)(bm + tm0 + i) * N_DIM + bn + tn0;
        float4 r0, r1;
        r0.x = acc[i][0] + bv[0];
        r0.y = acc[i][1] + bv[1];
        r0.z = acc[i][2] + bv[2];
        r0.w = acc[i][3] + bv[3];
        r1.x = acc[i][4] + bv[4];
        r1.y = acc[i][5] + bv[5];
        r1.z = acc[i][6] + bv[6];
        r1.w = acc[i][7] + bv[7];
        *reinterpret_cast<float4*>(&out[base])     = r0;
        *reinterpret_cast<float4*>(&out[base + 4]) = r1;
    }
}

// ---------------------------------------------------------------------------
// Launch
// inputs (metadata order): 0=x f32 [4,2048,4096], 1=weight_packed i32 [4096,2048],
//                          2=scales f32 [4096,32], 3=zeros f32 (unused), 4=bias f32 [4096]
// output: f32 [4,2048,4096]
// ---------------------------------------------------------------------------
extern "C" void kernel_launch(void* const* d_in, const int* in_sizes, int n_in,
                              void* d_out, int out_size) {
    const float* x      = (const float*)d_in[0];
    const int*   wp     = (const int*)d_in[1];
    const float* scales = (const float*)d_in[2];
    const float* bias   = (const float*)d_in[4];
    float*       out    = (float*)d_out;

    (void)in_sizes; (void)n_in; (void)out_size;

    // 1) dequantize weights into g_W
    {
        int total = N_DIM * PACKED_PER_ROW;
        int threads = 256;
        int blocks = (total + threads - 1) / threads;
        dequant_kernel<<<blocks, threads>>>(wp, scales);
    }

    // 2) SGEMM
    {
        dim3 grid(N_DIM / BN, M_DIM / BM);  // (32, 64)
        sgemm_kernel<<<grid, 256>>>(x, bias, out);
    }
}

// round 3
// speedup vs baseline: 5.8242x; 5.8242x over previous
#include <cuda_runtime.h>
#include <cuda_fp16.h>
#include <cstdint>

// ---------------- problem constants ----------------
#define K_DIM 4096
#define N_DIM 4096
#define M_DIM 8192            // 4 * 2048
#define GROUPS 32
#define PACKED_PER_ROW 2048   // K/2

// ---------------- GEMM tiling ----------------
#define BM 128
#define BN 128
#define BK 32                 // halves per K-chunk
#define NCHUNK (K_DIM / BK)   // 128
#define LDS_ROW 40            // halves per SMEM row (32 + 8 pad) = 80 bytes

// fp16 scratch (static __device__ — no runtime allocation)
__device__ __half g_Wh[(size_t)N_DIM * K_DIM];   // 32 MB
__device__ __half g_Xh[(size_t)M_DIM * K_DIM];   // 64 MB

// ---------------- PTX helpers (baseline sm_80+ features only) ----------------
__device__ __forceinline__ uint32_t smem_u32(const void* p) {
    uint32_t a;
    asm("{ .reg .u64 t; cvta.to.shared.u64 t, %1; cvt.u32.u64 %0, t; }" : "=r"(a) : "l"(p));
    return a;
}

#define CP_ASYNC16(dst, src) \
    asm volatile("cp.async.cg.shared.global [%0], [%1], 16;\n" :: "r"(dst), "l"(src))
#define CP_COMMIT()  asm volatile("cp.async.commit_group;\n" ::: "memory")
#define CP_WAIT(n)   asm volatile("cp.async.wait_group %0;\n" :: "n"(n) : "memory")

__device__ __forceinline__ void ldsm_x4(uint32_t& r0, uint32_t& r1,
                                        uint32_t& r2, uint32_t& r3, uint32_t addr) {
    asm volatile("ldmatrix.sync.aligned.m8n8.x4.shared.b16 {%0,%1,%2,%3}, [%4];"
                 : "=r"(r0), "=r"(r1), "=r"(r2), "=r"(r3) : "r"(addr));
}

__device__ __forceinline__ void mma_16816(float* d, const uint32_t* a,
                                          const uint32_t* b) {
    asm volatile(
        "mma.sync.aligned.m16n8k16.row.col.f32.f16.f16.f32 "
        "{%0,%1,%2,%3}, {%4,%5,%6,%7}, {%8,%9}, {%0,%1,%2,%3};"
        : "+f"(d[0]), "+f"(d[1]), "+f"(d[2]), "+f"(d[3])
        : "r"(a[0]), "r"(a[1]), "r"(a[2]), "r"(a[3]), "r"(b[0]), "r"(b[1]));
}

// ---------------- SMEM layout (dynamic) ----------------
// A tile: 128 rows x 40 halves = 10240 B, B tile same. Double-buffered.
#define ATILE_B (BM * LDS_ROW * 2)
#define SM_A0 0
#define SM_B0 (SM_A0 + ATILE_B)
#define SM_A1 (SM_B0 + ATILE_B)
#define SM_B1 (SM_A1 + ATILE_B)
#define SM_TOTAL (SM_B1 + ATILE_B)    // 40960 bytes

// ---------------------------------------------------------------------------
// Prep kernel 1: packed int4 -> fp16 dequantized weights
// ---------------------------------------------------------------------------
__global__ void dequant_f16(const int* __restrict__ wp,
                            const float* __restrict__ scales) {
    int idx = blockIdx.x * blockDim.x + threadIdx.x;
    if (idx >= N_DIM * PACKED_PER_ROW) return;
    int o = idx >> 11;
    int j = idx & 2047;
    int p = wp[idx];
    float s = scales[o * GROUPS + (j >> 6)];
    __half lo = __float2half_rn((float)((p & 15) - 8) * s);
    __half hi = __float2half_rn((float)(((p >> 4) & 15) - 8) * s);
    reinterpret_cast<__half2*>(g_Wh)[idx] = __halves2half2(lo, hi);
}

// ---------------------------------------------------------------------------
// Prep kernel 2: x fp32 -> fp16
// ---------------------------------------------------------------------------
__global__ void convert_x(const float* __restrict__ x) {
    int idx = blockIdx.x * blockDim.x + threadIdx.x;  // over M*K/4
    if (idx >= (M_DIM * K_DIM) / 4) return;
    float4 v = reinterpret_cast<const float4*>(x)[idx];
    __half2 a = __floats2half2_rn(v.x, v.y);
    __half2 b = __floats2half2_rn(v.z, v.w);
    uint2 u;
    u.x = *reinterpret_cast<uint32_t*>(&a);
    u.y = *reinterpret_cast<uint32_t*>(&b);
    reinterpret_cast<uint2*>(g_Xh)[idx] = u;
}

// ---------------------------------------------------------------------------
// HMMA fp16 GEMM: out[m][o] = sum_k Xh[m][k] * Wh[o][k] + bias[o]
// 128x128 CTA tile, BK=32, 8 warps (2x4), warp tile 64x32.
// ---------------------------------------------------------------------------
__global__ void __launch_bounds__(256, 2)
gemm_hmma(const float* __restrict__ bias, float* __restrict__ out) {
    extern __shared__ char smem[];
    const uint32_t sb = smem_u32(smem);
    const int tid  = threadIdx.x;
    const int lane = tid & 31;
    const int wid  = tid >> 5;
    const int warp_m = wid >> 2;            // 0..1
    const int warp_n = wid & 3;             // 0..3
    const int wm0 = warp_m * 64;
    const int wn0 = warp_n * 32;
    const int bm = blockIdx.y * BM;
    const int bn = blockIdx.x * BN;

    const char* Xbase = (const char*)(g_Xh + (size_t)bm * K_DIM);
    const char* Wbase = (const char*)(g_Wh + (size_t)bn * K_DIM);

    // cp.async load indexing: idx 0..511 per tile; row = idx>>2, seg16 = idx&3
    const int ld_row = tid >> 2;            // base row for t=0 (rows 0..63)
    const int ld_seg = tid & 3;

    auto load_chunk = [&](int c, int buf) {
        uint32_t abase = sb + (buf ? SM_A1 : SM_A0);
        uint32_t bbase = sb + (buf ? SM_B1 : SM_B0);
        const char* asrc = Xbase + c * (BK * 2);
        const char* bsrc = Wbase + c * (BK * 2);
        #pragma unroll
        for (int t = 0; t < 2; t++) {
            int row = ld_row + t * 64;
            uint32_t doff = (row * LDS_ROW + ld_seg * 8) * 2;  // seg16 = 8 halves
            size_t   soff = (size_t)row * (K_DIM * 2) + ld_seg * 16;
            CP_ASYNC16(abase + doff, asrc + soff);
            CP_ASYNC16(bbase + doff, bsrc + soff);
        }
        CP_COMMIT();
    };

    // ldmatrix per-lane byte offsets within a tile (k-step 0)
    // row = tile_row_base + (lane & 15); col16 = (lane >> 4) * 8 halves
    uint32_t aoff[4], boff[2];
    #pragma unroll
    for (int mi = 0; mi < 4; mi++)
        aoff[mi] = ((wm0 + mi * 16 + (lane & 15)) * LDS_ROW + ((lane >> 4) << 3)) * 2;
    #pragma unroll
    for (int nj = 0; nj < 2; nj++)
        boff[nj] = ((wn0 + nj * 16 + (lane & 15)) * LDS_ROW + ((lane >> 4) << 3)) * 2;

    float acc[4][4][4];
    #pragma unroll
    for (int i = 0; i < 4; i++)
        #pragma unroll
        for (int j = 0; j < 4; j++)
            #pragma unroll
            for (int q = 0; q < 4; q++)
                acc[i][j][q] = 0.0f;

    load_chunk(0, 0);

    int buf = 0;
    for (int c = 0; c < NCHUNK; c++) {
        if (c + 1 < NCHUNK) {
            load_chunk(c + 1, buf ^ 1);
            CP_WAIT(1);
        } else {
            CP_WAIT(0);
        }
        __syncthreads();

        uint32_t abase = sb + (buf ? SM_A1 : SM_A0);
        uint32_t bbase = sb + (buf ? SM_B1 : SM_B0);

        #pragma unroll
        for (int ks = 0; ks < 2; ks++) {            // two k16 steps in BK=32
            uint32_t koff = ks * 32;                // 16 halves = 32 bytes
            uint32_t a[4][4], b[4][2];
            #pragma unroll
            for (int mi = 0; mi < 4; mi++)
                ldsm_x4(a[mi][0], a[mi][1], a[mi][2], a[mi][3],
                        abase + aoff[mi] + koff);
            #pragma unroll
            for (int njp = 0; njp < 2; njp++) {
                uint32_t r0, r1, r2, r3;
                ldsm_x4(r0, r1, r2, r3, bbase + boff[njp] + koff);
                b[njp * 2 + 0][0] = r0; b[njp * 2 + 0][1] = r2;
                b[njp * 2 + 1][0] = r1; b[njp * 2 + 1][1] = r3;
            }
            #pragma unroll
            for (int mi = 0; mi < 4; mi++)
                #pragma unroll
                for (int nj = 0; nj < 4; nj++)
                    mma_16816(acc[mi][nj], a[mi], b[nj]);
        }
        __syncthreads();
        buf ^= 1;
    }

    // ---- epilogue: bias + direct global stores (float2 per fragment row) ----
    const int row0 = lane >> 2;
    const int col0 = (lane & 3) * 2;
    float2 bv[4];
    #pragma unroll
    for (int nj = 0; nj < 4; nj++) {
        int n = bn + wn0 + nj * 8 + col0;
        bv[nj].x = __ldg(&bias[n]);
        bv[nj].y = __ldg(&bias[n + 1]);
    }
    #pragma unroll
    for (int mi = 0; mi < 4; mi++) {
        int m = bm + wm0 + mi * 16 + row0;
        #pragma unroll
        for (int nj = 0; nj < 4; nj++) {
            int n = bn + wn0 + nj * 8 + col0;
            float2 v0 = make_float2(acc[mi][nj][0] + bv[nj].x,
                                    acc[mi][nj][1] + bv[nj].y);
            float2 v1 = make_float2(acc[mi][nj][2] + bv[nj].x,
                                    acc[mi][nj][3] + bv[nj].y);
            *reinterpret_cast<float2*>(&out[(size_t)m * N_DIM + n]) = v0;
            *reinterpret_cast<float2*>(&out[(size_t)(m + 8) * N_DIM + n]) = v1;
        }
    }
}

// ---------------------------------------------------------------------------
// Launch
// inputs: 0=x f32 [4,2048,4096], 1=weight_packed i32 [4096,2048],
//         2=scales f32 [4096,32], 3=zeros (unused), 4=bias f32 [4096]
// output: f32 [4,2048,4096]
// ---------------------------------------------------------------------------
extern "C" void kernel_launch(void* const* d_in, const int* in_sizes, int n_in,
                              void* d_out, int out_size) {
    const float* x      = (const float*)d_in[0];
    const int*   wp     = (const int*)d_in[1];
    const float* scales = (const float*)d_in[2];
    const float* bias   = (const float*)d_in[4];
    float*       out    = (float*)d_out;
    (void)in_sizes; (void)n_in; (void)out_size;

    {   // dequant W -> fp16
        int total = N_DIM * PACKED_PER_ROW;
        dequant_f16<<<(total + 255) / 256, 256>>>(wp, scales);
    }
    {   // convert X -> fp16
        int total = (M_DIM * K_DIM) / 4;
        convert_x<<<(total + 255) / 256, 256>>>(x);
    }
    {   // HMMA GEMM
        static bool attr_set = false;
        if (!attr_set) {
            cudaFuncSetAttribute(gemm_hmma,
                                 cudaFuncAttributeMaxDynamicSharedMemorySize,
                                 SM_TOTAL);
            attr_set = true;
        }
        dim3 grid(N_DIM / BN, M_DIM / BM);   // (32, 64)
        gemm_hmma<<<grid, 256, SM_TOTAL>>>(bias, out);
    }
}

// round 4
// speedup vs baseline: 6.6384x; 1.1398x over previous
#include <cuda_runtime.h>
#include <cuda_fp16.h>
#include <cstdint>

// ---------------- problem constants ----------------
#define K_DIM 4096
#define N_DIM 4096
#define M_DIM 8192            // 4 * 2048
#define GROUPS 32
#define PACKED_PER_ROW 2048   // K/2

// ---------------- GEMM tiling ----------------
#define BM 128
#define BN 128
#define BK 64                 // halves per K-chunk (128 bytes per row)
#define NCHUNK (K_DIM / BK)   // 64
#define LDS_ROW 72            // halves per SMEM row (64 + 8 pad) = 144 bytes

// fp16 scratch (static __device__ — no runtime allocation)
__device__ __half g_Wh[(size_t)N_DIM * K_DIM];   // 32 MB
__device__ __half g_Xh[(size_t)M_DIM * K_DIM];   // 64 MB

// ---------------- PTX helpers (baseline sm_80+ features only) ----------------
__device__ __forceinline__ uint32_t smem_u32(const void* p) {
    uint32_t a;
    asm("{ .reg .u64 t; cvta.to.shared.u64 t, %1; cvt.u32.u64 %0, t; }" : "=r"(a) : "l"(p));
    return a;
}

#define CP_ASYNC16(dst, src) \
    asm volatile("cp.async.cg.shared.global [%0], [%1], 16;\n" :: "r"(dst), "l"(src))
#define CP_COMMIT()  asm volatile("cp.async.commit_group;\n" ::: "memory")
#define CP_WAIT(n)   asm volatile("cp.async.wait_group %0;\n" :: "n"(n) : "memory")

__device__ __forceinline__ void ldsm_x4(uint32_t& r0, uint32_t& r1,
                                        uint32_t& r2, uint32_t& r3, uint32_t addr) {
    asm volatile("ldmatrix.sync.aligned.m8n8.x4.shared.b16 {%0,%1,%2,%3}, [%4];"
                 : "=r"(r0), "=r"(r1), "=r"(r2), "=r"(r3) : "r"(addr));
}

__device__ __forceinline__ void mma_16816(float* d, const uint32_t* a,
                                          const uint32_t* b) {
    asm volatile(
        "mma.sync.aligned.m16n8k16.row.col.f32.f16.f16.f32 "
        "{%0,%1,%2,%3}, {%4,%5,%6,%7}, {%8,%9}, {%0,%1,%2,%3};"
        : "+f"(d[0]), "+f"(d[1]), "+f"(d[2]), "+f"(d[3])
        : "r"(a[0]), "r"(a[1]), "r"(a[2]), "r"(a[3]), "r"(b[0]), "r"(b[1]));
}

// ---------------- SMEM layout (dynamic) ----------------
// Tile: 128 rows x 72 halves = 18432 B per matrix. Double-buffered.
#define TILE_B (BM * LDS_ROW * 2)      // 18432
#define SM_A0 0
#define SM_B0 (SM_A0 + TILE_B)
#define SM_A1 (SM_B0 + TILE_B)
#define SM_B1 (SM_A1 + TILE_B)
#define SM_TOTAL (SM_B1 + TILE_B)      // 73728 bytes -> 2 CTAs/SM

// ---------------------------------------------------------------------------
// Prep kernel 1: packed int4 -> fp16 dequantized weights (16B in / 16B out)
// ---------------------------------------------------------------------------
__global__ void dequant_f16(const int* __restrict__ wp,
                            const float* __restrict__ scales) {
    int idx = blockIdx.x * blockDim.x + threadIdx.x;   // over N*PACKED/4
    if (idx >= (N_DIM * PACKED_PER_ROW) / 4) return;
    int4 p = reinterpret_cast<const int4*>(wp)[idx];
    int j4 = idx << 2;                 // first packed column index *within all*
    int o = j4 >> 11;
    int j = j4 & 2047;
    float s = scales[o * GROUPS + (j >> 6)];   // 4 consecutive j share a group
    uint4 v;
    {
        __half2 h = __halves2half2(__float2half_rn((float)((p.x & 15) - 8) * s),
                                   __float2half_rn((float)(((p.x >> 4) & 15) - 8) * s));
        v.x = *reinterpret_cast<uint32_t*>(&h);
    }
    {
        __half2 h = __halves2half2(__float2half_rn((float)((p.y & 15) - 8) * s),
                                   __float2half_rn((float)(((p.y >> 4) & 15) - 8) * s));
        v.y = *reinterpret_cast<uint32_t*>(&h);
    }
    {
        __half2 h = __halves2half2(__float2half_rn((float)((p.z & 15) - 8) * s),
                                   __float2half_rn((float)(((p.z >> 4) & 15) - 8) * s));
        v.z = *reinterpret_cast<uint32_t*>(&h);
    }
    {
        __half2 h = __halves2half2(__float2half_rn((float)((p.w & 15) - 8) * s),
                                   __float2half_rn((float)(((p.w >> 4) & 15) - 8) * s));
        v.w = *reinterpret_cast<uint32_t*>(&h);
    }
    reinterpret_cast<uint4*>(g_Wh)[idx] = v;
}

// ---------------------------------------------------------------------------
// Prep kernel 2: x fp32 -> fp16 (32B in / 16B out per thread)
// ---------------------------------------------------------------------------
__global__ void convert_x(const float* __restrict__ x) {
    int idx = blockIdx.x * blockDim.x + threadIdx.x;   // over M*K/8
    if (idx >= (M_DIM * K_DIM) / 8) return;
    float4 v0 = reinterpret_cast<const float4*>(x)[2 * idx];
    float4 v1 = reinterpret_cast<const float4*>(x)[2 * idx + 1];
    __half2 a = __floats2half2_rn(v0.x, v0.y);
    __half2 b = __floats2half2_rn(v0.z, v0.w);
    __half2 c = __floats2half2_rn(v1.x, v1.y);
    __half2 d = __floats2half2_rn(v1.z, v1.w);
    uint4 u;
    u.x = *reinterpret_cast<uint32_t*>(&a);
    u.y = *reinterpret_cast<uint32_t*>(&b);
    u.z = *reinterpret_cast<uint32_t*>(&c);
    u.w = *reinterpret_cast<uint32_t*>(&d);
    reinterpret_cast<uint4*>(g_Xh)[idx] = u;
}

// ---------------------------------------------------------------------------
// HMMA fp16 GEMM: out[m][o] = sum_k Xh[m][k] * Wh[o][k] + bias[o]
// 128x128 CTA tile, BK=64, 8 warps (2x4), warp tile 64x32.
// Double-buffered cp.async, ONE __syncthreads per k-chunk.
// ---------------------------------------------------------------------------
__global__ void __launch_bounds__(256, 2)
gemm_hmma(const float* __restrict__ bias, float* __restrict__ out) {
    extern __shared__ char smem[];
    const uint32_t sb = smem_u32(smem);
    const int tid  = threadIdx.x;
    const int lane = tid & 31;
    const int wid  = tid >> 5;
    const int wm0 = (wid >> 2) * 64;        // warp_m 0..1
    const int wn0 = (wid & 3) * 32;         // warp_n 0..3
    const int bm = blockIdx.y * BM;
    const int bn = blockIdx.x * BN;

    const char* Xbase = (const char*)(g_Xh + (size_t)bm * K_DIM);
    const char* Wbase = (const char*)(g_Wh + (size_t)bn * K_DIM);

    // cp.async indexing: per matrix 128 rows x 8 segs(16B) = 1024 ops, 4/thread
    const int ld_row = tid >> 3;            // rows 0..31 (t adds 32)
    const int ld_seg = tid & 7;

    auto load_chunk = [&](int c, int buf) {
        uint32_t abase = sb + (buf ? SM_A1 : SM_A0);
        uint32_t bbase = sb + (buf ? SM_B1 : SM_B0);
        const char* asrc = Xbase + c * (BK * 2);
        const char* bsrc = Wbase + c * (BK * 2);
        #pragma unroll
        for (int t = 0; t < 4; t++) {
            int row = ld_row + t * 32;
            uint32_t doff = row * (LDS_ROW * 2) + ld_seg * 16;
            size_t   soff = (size_t)row * (K_DIM * 2) + ld_seg * 16;
            CP_ASYNC16(abase + doff, asrc + soff);
            CP_ASYNC16(bbase + doff, bsrc + soff);
        }
        CP_COMMIT();
    };

    // ldmatrix per-lane byte offsets (k-step 0): row = base + (lane&15),
    // col16 = (lane>>4)*8 halves
    uint32_t aoff[4], boff[2];
    #pragma unroll
    for (int mi = 0; mi < 4; mi++)
        aoff[mi] = (wm0 + mi * 16 + (lane & 15)) * (LDS_ROW * 2)
                 + ((lane >> 4) << 4);
    #pragma unroll
    for (int nj = 0; nj < 2; nj++)
        boff[nj] = (wn0 + nj * 16 + (lane & 15)) * (LDS_ROW * 2)
                 + ((lane >> 4) << 4);

    float acc[4][4][4];
    #pragma unroll
    for (int i = 0; i < 4; i++)
        #pragma unroll
        for (int j = 0; j < 4; j++)
            #pragma unroll
            for (int q = 0; q < 4; q++)
                acc[i][j][q] = 0.0f;

    load_chunk(0, 0);

    int buf = 0;
    for (int c = 0; c < NCHUNK; c++) {
        CP_WAIT(0);
        __syncthreads();      // stage c ready; all warps done with stage c-1

        if (c + 1 < NCHUNK)
            load_chunk(c + 1, buf ^ 1);   // safe: overwrites stage c-1 buffer

        uint32_t abase = sb + (buf ? SM_A1 : SM_A0);
        uint32_t bbase = sb + (buf ? SM_B1 : SM_B0);

        #pragma unroll
        for (int ks = 0; ks < 4; ks++) {            // four k16 steps in BK=64
            uint32_t koff = ks * 32;                // 16 halves = 32 bytes
            uint32_t a[4][4], b[4][2];
            #pragma unroll
            for (int mi = 0; mi < 4; mi++)
                ldsm_x4(a[mi][0], a[mi][1], a[mi][2], a[mi][3],
                        abase + aoff[mi] + koff);
            #pragma unroll
            for (int njp = 0; njp < 2; njp++) {
                uint32_t r0, r1, r2, r3;
                ldsm_x4(r0, r1, r2, r3, bbase + boff[njp] + koff);
                b[njp * 2 + 0][0] = r0; b[njp * 2 + 0][1] = r2;
                b[njp * 2 + 1][0] = r1; b[njp * 2 + 1][1] = r3;
            }
            #pragma unroll
            for (int mi = 0; mi < 4; mi++)
                #pragma unroll
                for (int nj = 0; nj < 4; nj++)
                    mma_16816(acc[mi][nj], a[mi], b[nj]);
        }
        buf ^= 1;
    }

    // ---- epilogue: bias + direct global stores (float2 per fragment row) ----
    const int row0 = lane >> 2;
    const int col0 = (lane & 3) * 2;
    float2 bv[4];
    #pragma unroll
    for (int nj = 0; nj < 4; nj++) {
        int n = bn + wn0 + nj * 8 + col0;
        bv[nj].x = __ldg(&bias[n]);
        bv[nj].y = __ldg(&bias[n + 1]);
    }
    #pragma unroll
    for (int mi = 0; mi < 4; mi++) {
        int m = bm + wm0 + mi * 16 + row0;
        #pragma unroll
        for (int nj = 0; nj < 4; nj++) {
            int n = bn + wn0 + nj * 8 + col0;
            float2 v0 = make_float2(acc[mi][nj][0] + bv[nj].x,
                                    acc[mi][nj][1] + bv[nj].y);
            float2 v1 = make_float2(acc[mi][nj][2] + bv[nj].x,
                                    acc[mi][nj][3] + bv[nj].y);
            *reinterpret_cast<float2*>(&out[(size_t)m * N_DIM + n]) = v0;
            *reinterpret_cast<float2*>(&out[(size_t)(m + 8) * N_DIM + n]) = v1;
        }
    }
}

// ---------------------------------------------------------------------------
// Launch
// inputs: 0=x f32, 1=weight_packed i32, 2=scales f32, 3=zeros, 4=bias f32
// output: f32 [4,2048,4096]
// ---------------------------------------------------------------------------
extern "C" void kernel_launch(void* const* d_in, const int* in_sizes, int n_in,
                              void* d_out, int out_size) {
    const float* x      = (const float*)d_in[0];
    const int*   wp     = (const int*)d_in[1];
    const float* scales = (const float*)d_in[2];
    const float* bias   = (const float*)d_in[4];
    float*       out    = (float*)d_out;
    (void)in_sizes; (void)n_in; (void)out_size;

    {   // dequant W -> fp16
        int total = (N_DIM * PACKED_PER_ROW) / 4;
        dequant_f16<<<(total + 255) / 256, 256>>>(wp, scales);
    }
    {   // convert X -> fp16
        int total = (M_DIM * K_DIM) / 8;
        convert_x<<<(total + 255) / 256, 256>>>(x);
    }
    {   // HMMA GEMM
        static bool attr_set = false;
        if (!attr_set) {
            cudaFuncSetAttribute(gemm_hmma,
                                 cudaFuncAttributeMaxDynamicSharedMemorySize,
                                 SM_TOTAL);
            attr_set = true;
        }
        dim3 grid(N_DIM / BN, M_DIM / BM);   // (32, 64)
        gemm_hmma<<<grid, 256, SM_TOTAL>>>(bias, out);
    }
}